// round 15
// baseline (speedup 1.0000x reference)
#include <cuda_runtime.h>
#include <cuda_bf16.h>
#include <cstdint>

#define Bq 16
#define Tt 8192
#define Dd 512
#define Aa 512
#define NROWS (Bq * Tt)
#define NEGINF (-3.4028234663852886e+38f)
#define EPSV 1e-8f

// -------------------- device scratch (no allocation allowed) ----------------
__device__ __align__(1024) __nv_bfloat16 g_wt[2 * Aa * Dd]; // W^T bf16: [set][a][k]
__device__ float g_qk[2][Bq][Aa];
__device__ float g_vw[2][Aa];
__device__ float g_e[2][NROWS];
__device__ float g_cvp[64][Bq][Dd];

// -------------------- helpers ----------------------------------------------
__device__ __forceinline__ uint32_t smem_to_u32(const void* p) {
    uint32_t a;
    asm("{ .reg .u64 t; cvta.to.shared.u64 t, %1; cvt.u32.u64 %0, t; }" : "=r"(a) : "l"(p));
    return a;
}
__device__ __forceinline__ float tanh_fast(float x) {
    float y;
    asm("tanh.approx.f32 %0, %1;" : "=f"(y) : "f"(x));
    return y;
}
__device__ __forceinline__ void ldsm4(uint32_t& r0, uint32_t& r1, uint32_t& r2, uint32_t& r3,
                                      uint32_t addr) {
    asm volatile("ldmatrix.sync.aligned.m8n8.x4.shared.b16 {%0,%1,%2,%3}, [%4];"
                 : "=r"(r0), "=r"(r1), "=r"(r2), "=r"(r3) : "r"(addr));
}
__device__ __forceinline__ void mma16816(float* d, const uint32_t* a, uint32_t b0, uint32_t b1) {
    asm volatile(
        "mma.sync.aligned.m16n8k16.row.col.f32.bf16.bf16.f32 "
        "{%0,%1,%2,%3}, {%4,%5,%6,%7}, {%8,%9}, {%0,%1,%2,%3};"
        : "+f"(d[0]), "+f"(d[1]), "+f"(d[2]), "+f"(d[3])
        : "r"(a[0]), "r"(a[1]), "r"(a[2]), "r"(a[3]), "r"(b0), "r"(b1));
}
__device__ __forceinline__ void cp_async16(uint32_t smem_addr, const void* gptr) {
    asm volatile("cp.async.cg.shared.global [%0], [%1], 16;"
                 :: "r"(smem_addr), "l"(__cvta_generic_to_global(gptr)) : "memory");
}
__device__ __forceinline__ void mbar_init(uint32_t addr, uint32_t count) {
    asm volatile("mbarrier.init.shared.b64 [%0], %1;" :: "r"(addr), "r"(count) : "memory");
}
__device__ __forceinline__ void cp_async_mbar_arrive(uint32_t addr) {
    asm volatile("cp.async.mbarrier.arrive.noinc.shared.b64 [%0];" :: "r"(addr) : "memory");
}
__device__ __forceinline__ void mbar_arrive(uint32_t addr) {
    asm volatile("mbarrier.arrive.shared.b64 _, [%0];" :: "r"(addr) : "memory");
}
#define MBAR_WAIT(addr, parity) do { \
    uint32_t _mbar = (addr); \
    uint32_t _parity = (parity); \
    uint32_t _done; \
    asm volatile("{\n\t.reg .pred p;\n\t" \
        "mbarrier.try_wait.parity.acquire.cta.shared::cta.b64 p, [%1], %2;\n\t" \
        "selp.b32 %0, 1, 0, p;\n\t}" : "=r"(_done) : "r"(_mbar), "r"(_parity) : "memory"); \
    if (!_done) { \
        asm volatile("{\n\t.reg .pred P1;\n\t" \
            "WAIT_LOOP_%=:\n\t" \
            "mbarrier.try_wait.parity.acquire.cta.shared::cta.b64 P1, [%0], %1, 0x989680;\n\t" \
            "@P1 bra.uni WAIT_DONE_%=;\n\t" \
            "bra.uni WAIT_LOOP_%=;\n\t" \
            "WAIT_DONE_%=:\n\t}" :: "r"(_mbar), "r"(_parity) : "memory"); \
    } \
} while (0)

// ---------- merged prepass: vw | qk | W^T pack in one kernel ----------------
__global__ void __launch_bounds__(512) prep_all_kernel(
    const float* __restrict__ query,
    const float* __restrict__ m_wk, const float* __restrict__ m_bk,
    const float* __restrict__ m_wq, const float* __restrict__ m_vv,
    const float* __restrict__ m_vg,
    const float* __restrict__ c_wk, const float* __restrict__ c_bk,
    const float* __restrict__ c_wq, const float* __restrict__ c_vv,
    const float* __restrict__ c_vg) {
    int blk = blockIdx.x;
    int tid = threadIdx.x;
    if (blk < 2) {
        int set = blk;
        const float* vv = set ? c_vv : m_vv;
        float g = set ? __ldg(c_vg) : __ldg(m_vg);
        float v = vv[tid];
        float ss = v * v;
        __shared__ float sc[32];
        int lane = tid & 31, w = tid >> 5;
        #pragma unroll
        for (int o = 16; o > 0; o >>= 1) ss += __shfl_down_sync(0xffffffffu, ss, o);
        if (lane == 0) sc[w] = ss;
        __syncthreads();
        if (w == 0) {
            float x = (lane < 16) ? sc[lane] : 0.f;
            #pragma unroll
            for (int o = 8; o > 0; o >>= 1) x += __shfl_down_sync(0xffffffffu, x, o);
            if (lane == 0) sc[0] = x;
        }
        __syncthreads();
        g_vw[set][tid] = g / sqrtf(sc[0]) * v;
    } else if (blk < 34) {
        int id = blk - 2;
        int b = id & 15, set = id >> 4;
        const float* wq = set ? c_wq : m_wq;
        const float* bk = set ? c_bk : m_bk;
        __shared__ float qs[Dd];
        qs[tid] = query[(size_t)b * Dd + tid];
        __syncthreads();
        float acc = 0.f;
        #pragma unroll 8
        for (int d = 0; d < Dd; d++) acc = fmaf(qs[d], wq[(size_t)d * Aa + tid], acc);
        g_qk[set][b][tid] = acc + bk[tid];
    } else {
        int id = blk - 34;
        int k0 = (id & 31) * 16;
        int set = id >> 5;
        const float* wk = set ? c_wk : m_wk;
        __nv_bfloat16* img = g_wt + (size_t)set * Aa * Dd;
        #pragma unroll
        for (int i = 0; i < 16; i++) {
            int idx = tid + i * 512;
            int kk = idx >> 9;
            int a = idx & 511;
            float v = wk[(size_t)(k0 + kk) * Aa + a];
            img[(size_t)a * Dd + (k0 + kk)] = __float2bfloat16_rn(v);
        }
    }
}

// --- energy kernel: mbarrier producer-consumer pipeline (no syncthreads loop)
// SMEM: A 65536 | B 3 stages x 16384 = 49152 | e_red 512 | mbar 48
#define SM_A 0u
#define SM_B0 65536u
#define SM_ER 114688u
#define SM_MB 115200u
#define ENERGY_SMEM 115264
__global__ void __launch_bounds__(256, 2) energy_kernel(
    const float* __restrict__ key,
    const float* __restrict__ m_vb, const float* __restrict__ m_r,
    const float* __restrict__ c_vb, const float* __restrict__ c_r) {
    extern __shared__ __align__(1024) unsigned char smem[];
    const uint32_t sbase = smem_to_u32(smem);
    const int tid = threadIdx.x;
    const int lane = tid & 31, wid = tid >> 5; // 8 warps, side-by-side in N
    const int warpN = wid * 32;
    const int mtile = blockIdx.x;              // 2048 tiles of 64 rows
    const int b = mtile >> 7;

    float* e_red = reinterpret_cast<float*>(smem + SM_ER); // [set][64]
    const uint32_t fullb = sbase + SM_MB;
    const uint32_t emptyb = sbase + SM_MB + 24;

    if (tid < 3) mbar_init(fullb + tid * 8, 256);
    else if (tid < 6) mbar_init(emptyb + (tid - 3) * 8, 256);
    if (tid < 128) e_red[tid] = 0.f;

    // ---- A tile: 64 rows of key, fp32 -> bf16, layout (k>>6)*8KB + r*128 + (k&63)*2, xor swz
    const float* krow = key + (size_t)mtile * 64 * Dd;
    for (int idx = tid; idx < 64 * 256; idx += 256) {
        int r = idx >> 8;
        int c2 = (idx & 255) << 1;
        float2 v = *reinterpret_cast<const float2*>(krow + (size_t)r * Dd + c2);
        __nv_bfloat162 bv;
        bv.x = __float2bfloat16_rn(v.x);
        bv.y = __float2bfloat16_rn(v.y);
        uint32_t off = (uint32_t)((c2 >> 6) * 8192 + r * 128 + (c2 & 63) * 2);
        off ^= (off >> 3) & 0x70;
        *reinterpret_cast<uint32_t*>(smem + SM_A + off) = *reinterpret_cast<uint32_t*>(&bv);
    }

    // A ldmatrix per-thread base addresses (4 m16 tiles = full 64 rows)
    const int arow0 = lane & 15;
    const uint32_t alp = (uint32_t)((lane >> 4) * 16);
    const uint32_t swzA = (uint32_t)((arow0 & 7) * 16);
    uint32_t aBase[4];
    #pragma unroll
    for (int mt = 0; mt < 4; mt++)
        aBase[mt] = sbase + SM_A + (uint32_t)((arow0 + mt * 16) * 128);

    // B buffer: 256 n-rows x 32 k bf16 (64B/row); chunk c at col (c ^ ((n>>1)&3))*16.
    const int nrow = (lane & 7) + ((lane >> 4) & 1) * 8;
    const uint32_t bsw = (uint32_t)((nrow >> 1) & 3);
    const uint32_t kb = (uint32_t)((lane >> 3) & 1);
    uint32_t bRow[2];
    #pragma unroll
    for (int p = 0; p < 2; p++)
        bRow[p] = (uint32_t)((warpN + nrow + p * 16) * 64);

    // cp.async per-thread slots: 4 rows x 16B per thread per k32-step (coalesced)
    const int bn = tid >> 2;  // row 0..63 (stride 64)
    const int bc = tid & 3;   // 16B chunk 0..3
    const uint32_t bcs = (uint32_t)((bc ^ ((bn >> 1) & 3)) << 4);
    uint32_t dstOff[4];
    #pragma unroll
    for (int i = 0; i < 4; i++)
        dstOff[i] = (uint32_t)((bn + i * 64) * 64) + bcs;
    const char* wtc = reinterpret_cast<const char*>(g_wt);

    __syncthreads(); // A visible; mbarriers inited; e_red zeroed

    uint32_t fp = 0u, ep = 7u; // per-buffer wait parities

    // step s -> set=s>>5, nc=(s>>4)&1, ks=s&15 ; buf=s%3
    #define ISSUE_B(s_) do { \
        int s__ = (s_); \
        int b2__ = s__ % 3; \
        MBAR_WAIT(emptyb + (uint32_t)(b2__ * 8), (ep >> b2__) & 1u); \
        ep ^= 1u << b2__; \
        const char* src__ = wtc + ((size_t)(s__ >> 5) << 19) \
            + (size_t)(((s__ >> 4) & 1) * 256 + bn) * 1024 \
            + (size_t)((s__ & 15) * 64) + bc * 16; \
        uint32_t dst__ = sbase + SM_B0 + (uint32_t)(b2__ * 16384); \
        cp_async16(dst__ + dstOff[0], src__); \
        cp_async16(dst__ + dstOff[1], src__ + 64 * 1024); \
        cp_async16(dst__ + dstOff[2], src__ + 128 * 1024); \
        cp_async16(dst__ + dstOff[3], src__ + 192 * 1024); \
        cp_async_mbar_arrive(fullb + (uint32_t)(b2__ * 8)); \
    } while (0)

    ISSUE_B(0);
    ISSUE_B(1);

    const float biasM = __ldg(m_vb) + __ldg(m_r);
    const float biasC = __ldg(c_vb) + __ldg(c_r);

    for (int seg = 0; seg < 4; seg++) {
        const int set = seg >> 1;
        const int n0 = (seg & 1) * 256;
        const float* qkp = g_qk[set][b];
        const float* vwp = g_vw[set];

        float acc[4][4][4];
        #pragma unroll
        for (int mt = 0; mt < 4; mt++)
            #pragma unroll
            for (int nt = 0; nt < 4; nt++)
                #pragma unroll
                for (int q = 0; q < 4; q++) acc[mt][nt][q] = 0.f;

        for (int ks = 0; ks < 16; ks++) {
            const int s = seg * 16 + ks;
            const int buf = s % 3;
            MBAR_WAIT(fullb + (uint32_t)(buf * 8), (fp >> buf) & 1u);
            fp ^= 1u << buf;

            const uint32_t aChunk = (uint32_t)((ks >> 1) * 8192);
            const uint32_t aHalf = (uint32_t)((ks & 1) * 64);
            const uint32_t bBufBase = sbase + SM_B0 + (uint32_t)(buf * 16384);
            #pragma unroll
            for (int g = 0; g < 2; g++) {   // k16 halves within k32
                uint32_t af[4][4];
                #pragma unroll
                for (int mt = 0; mt < 4; mt++) {
                    uint32_t addr = aBase[mt] + aChunk
                                    + ((aHalf + (uint32_t)(g * 32) + alp) ^ swzA);
                    ldsm4(af[mt][0], af[mt][1], af[mt][2], af[mt][3], addr);
                }
                const uint32_t bcol = (((uint32_t)(g * 2) + kb) ^ bsw) << 4;
                uint32_t bf[2][4];
                #pragma unroll
                for (int p = 0; p < 2; p++) {
                    uint32_t addr = bBufBase + bRow[p] + bcol;
                    ldsm4(bf[p][0], bf[p][1], bf[p][2], bf[p][3], addr);
                }
                #pragma unroll
                for (int mt = 0; mt < 4; mt++)
                    #pragma unroll
                    for (int nt = 0; nt < 4; nt++)
                        mma16816(acc[mt][nt], af[mt], bf[nt >> 1][(nt & 1) * 2],
                                 bf[nt >> 1][(nt & 1) * 2 + 1]);
            }
            mbar_arrive(emptyb + (uint32_t)(buf * 8));
            if (s + 2 < 64) ISSUE_B(s + 2);
        }

        // per-seg epilogue (warp-local): e += vw * tanh(acc + qk)
        float er[8];
        #pragma unroll
        for (int i = 0; i < 8; i++) er[i] = 0.f;
        #pragma unroll
        for (int mt = 0; mt < 4; mt++) {
            #pragma unroll
            for (int nt = 0; nt < 4; nt++) {
                int col = n0 + warpN + nt * 8 + (lane & 3) * 2;
                float q0 = __ldg(qkp + col), q1 = __ldg(qkp + col + 1);
                float w0 = __ldg(vwp + col), w1 = __ldg(vwp + col + 1);
                er[mt * 2 + 0] += w0 * tanh_fast(acc[mt][nt][0] + q0)
                                + w1 * tanh_fast(acc[mt][nt][1] + q1);
                er[mt * 2 + 1] += w0 * tanh_fast(acc[mt][nt][2] + q0)
                                + w1 * tanh_fast(acc[mt][nt][3] + q1);
            }
        }
        #pragma unroll
        for (int i = 0; i < 8; i++) {
            er[i] += __shfl_xor_sync(0xffffffffu, er[i], 1);
            er[i] += __shfl_xor_sync(0xffffffffu, er[i], 2);
        }
        if ((lane & 3) == 0) {
            int r = lane >> 2;
            #pragma unroll
            for (int mt = 0; mt < 4; mt++) {
                atomicAdd(&e_red[set * 64 + mt * 16 + r], er[mt * 2 + 0]);
                atomicAdd(&e_red[set * 64 + mt * 16 + r + 8], er[mt * 2 + 1]);
            }
        }
    }
    #undef ISSUE_B

    __syncthreads();
    if (tid < 128) {
        int set = tid >> 6, row = tid & 63;
        float bias = set ? biasC : biasM;
        g_e[set][(size_t)mtile * 64 + row] = e_red[tid] + bias;
    }
}

// -------------------- scan kernel (512 thr x 16 elem per batch) -------------
__device__ __forceinline__ float block_exscan512(float v, float* scratch) {
    int lane = threadIdx.x & 31, w = threadIdx.x >> 5;
    float x = v;
    #pragma unroll
    for (int o = 1; o < 32; o <<= 1) {
        float n = __shfl_up_sync(0xffffffffu, x, o);
        if (lane >= o) x += n;
    }
    if (lane == 31) scratch[w] = x;
    __syncthreads();
    if (w == 0) {
        float y = (lane < 16) ? scratch[lane] : 0.f;
        #pragma unroll
        for (int o = 1; o < 32; o <<= 1) {
            float n = __shfl_up_sync(0xffffffffu, y, o);
            if (lane >= o) y += n;
        }
        if (lane < 16) scratch[lane] = y;
    }
    __syncthreads();
    float pre = w ? scratch[w - 1] : 0.f;
    float r = pre + x - v;
    __syncthreads();
    return r;
}
__device__ __forceinline__ float block_max512(float v, float* scratch) {
    int lane = threadIdx.x & 31, w = threadIdx.x >> 5;
    float x = v;
    #pragma unroll
    for (int o = 16; o > 0; o >>= 1) x = fmaxf(x, __shfl_xor_sync(0xffffffffu, x, o));
    if (lane == 0) scratch[w] = x;
    __syncthreads();
    if (w == 0) {
        float y = (lane < 16) ? scratch[lane] : NEGINF;
        #pragma unroll
        for (int o = 16; o > 0; o >>= 1) y = fmaxf(y, __shfl_xor_sync(0xffffffffu, y, o));
        if (lane == 0) scratch[0] = y;
    }
    __syncthreads();
    float r = scratch[0];
    __syncthreads();
    return r;
}

#define SCAN_SMEM ((16384 + 32) * 4)
__global__ void __launch_bounds__(512) scan_kernel(
    const float* __restrict__ noise, const float* __restrict__ aw_prev,
    float* __restrict__ out) {
    extern __shared__ float sm[];
    float* se = sm;
    float* ratio = sm + 8192;
    float* scratch = sm + 16384;
    int b = blockIdx.x;
    int tid = threadIdx.x;
    int t0 = tid * 16;
    const float* em = g_e[0] + (size_t)b * Tt;
    const float* ec = g_e[1] + (size_t)b * Tt;
    const float* nz = noise + (size_t)b * Tt;
    const float* aw = aw_prev + (size_t)b * Tt;

    // NOTE: mask is jnp.ones(...) by construction — never read.
    float p[16], l1[16], cp[16], inn[16];
    float ts = 0.f;
    #pragma unroll
    for (int j = 0; j < 16; j++) {
        int t = t0 + j;
        float x = em[t] + nz[t];
        float pj = __fdividef(1.f, 1.f + __expf(-x));
        p[j] = pj;
        float om = fminf(fmaxf(1.f - pj, EPSV), 1.f);
        l1[j] = __logf(om);
        ts += l1[j];
    }
    float base = block_exscan512(ts, scratch);
    float run = base;
    float ts2 = 0.f;
    #pragma unroll
    for (int j = 0; j < 16; j++) {
        cp[j] = __expf(run);
        run += l1[j];
        float c = fminf(fmaxf(cp[j], EPSV), 1.f);
        inn[j] = __fdividef(aw[t0 + j], c);
        ts2 += inn[j];
    }
    float base2 = block_exscan512(ts2, scratch);
    float run2 = base2;
    #pragma unroll
    for (int j = 0; j < 16; j++) {
        run2 += inn[j];
        float a = p[j] * cp[j] * run2;
        p[j] = a;
        out[8192 + (size_t)b * Tt + t0 + j] = a;
    }

    float mx = NEGINF;
    #pragma unroll
    for (int j = 0; j < 16; j++) mx = fmaxf(mx, ec[t0 + j]);
    mx = block_max512(mx, scratch);
    #pragma unroll
    for (int j = 0; j < 16; j++) {
        int t = t0 + j;
        se[t] = fmaxf(__expf(ec[t] - mx), 1e-5f);
    }
    __syncthreads();
    #pragma unroll
    for (int j = 0; j < 16; j++) {
        int t = t0 + j;
        float d = se[t];
        if (t >= 1) d += se[t - 1];
        if (t >= 2) d += se[t - 2];
        if (t >= 3) d += se[t - 3];
        ratio[t] = __fdividef(p[j], d);
    }
    __syncthreads();
    #pragma unroll
    for (int j = 0; j < 16; j++) {
        int t = t0 + j;
        float s = ratio[t];
        if (t + 1 < Tt) s += ratio[t + 1];
        if (t + 2 < Tt) s += ratio[t + 2];
        if (t + 3 < Tt) s += ratio[t + 3];
        out[8192 + (size_t)NROWS + (size_t)b * Tt + t] = se[t] * s;
    }
}

// -------------------- cv = beta^T . value (float4 stream) -------------------
__global__ void __launch_bounds__(512) cv_partial_kernel(
    const float* __restrict__ value, const float* __restrict__ beta) {
    int tc = blockIdx.x, b = blockIdx.y;
    int d4 = threadIdx.x & 127;
    int tg = threadIdx.x >> 7;
    const float4* v = reinterpret_cast<const float4*>(
        value + ((size_t)b * Tt + (size_t)tc * 128) * Dd) + d4;
    const float* bt = beta + (size_t)b * Tt + (size_t)tc * 128 + tg * 32;
    float4 acc = make_float4(0.f, 0.f, 0.f, 0.f);
    #pragma unroll 8
    for (int t = 0; t < 32; t++) {
        float w = __ldg(bt + t);
        float4 x = __ldg(v + (size_t)(tg * 32 + t) * 128);
        acc.x = fmaf(w, x.x, acc.x);
        acc.y = fmaf(w, x.y, acc.y);
        acc.z = fmaf(w, x.z, acc.z);
        acc.w = fmaf(w, x.w, acc.w);
    }
    __shared__ float4 red[512];
    red[threadIdx.x] = acc;
    __syncthreads();
    if (tg == 0) {
        float4 a0 = red[d4], a1 = red[128 + d4], a2 = red[256 + d4], a3 = red[384 + d4];
        float4 s = make_float4(a0.x + a1.x + a2.x + a3.x,
                               a0.y + a1.y + a2.y + a3.y,
                               a0.z + a1.z + a2.z + a3.z,
                               a0.w + a1.w + a2.w + a3.w);
        reinterpret_cast<float4*>(g_cvp[tc][b])[d4] = s;
    }
}
__global__ void cv_reduce_kernel(float* __restrict__ out) {
    int b = blockIdx.x, d = threadIdx.x;
    float acc = 0.f;
    #pragma unroll
    for (int tc = 0; tc < 64; tc++) acc += g_cvp[tc][b][d];
    out[(size_t)b * Dd + d] = acc;
}

// -------------------- launch ------------------------------------------------
extern "C" void kernel_launch(void* const* d_in, const int* in_sizes, int n_in,
                              void* d_out, int out_size) {
    const float* key     = (const float*)d_in[0];
    const float* value   = (const float*)d_in[1];
    const float* query   = (const float*)d_in[2];
    const float* noise   = (const float*)d_in[3];
    const float* aw_prev = (const float*)d_in[4];
    // d_in[5] = mask: constant all-true — unused.
    const float* m_wk = (const float*)d_in[6];
    const float* m_bk = (const float*)d_in[7];
    const float* m_wq = (const float*)d_in[8];
    const float* m_vv = (const float*)d_in[9];
    const float* m_vg = (const float*)d_in[10];
    const float* m_vb = (const float*)d_in[11];
    const float* m_r  = (const float*)d_in[12];
    const float* c_wk = (const float*)d_in[13];
    const float* c_bk = (const float*)d_in[14];
    const float* c_wq = (const float*)d_in[15];
    const float* c_vv = (const float*)d_in[16];
    const float* c_vg = (const float*)d_in[17];
    const float* c_vb = (const float*)d_in[18];
    const float* c_r  = (const float*)d_in[19];
    float* out = (float*)d_out;

    cudaFuncSetAttribute(energy_kernel, cudaFuncAttributeMaxDynamicSharedMemorySize, ENERGY_SMEM);
    cudaFuncSetAttribute(scan_kernel, cudaFuncAttributeMaxDynamicSharedMemorySize, SCAN_SMEM);

    prep_all_kernel<<<98, 512>>>(query, m_wk, m_bk, m_wq, m_vv, m_vg,
                                 c_wk, c_bk, c_wq, c_vv, c_vg);
    energy_kernel<<<2048, 256, ENERGY_SMEM>>>(key, m_vb, m_r, c_vb, c_r);
    scan_kernel<<<16, 512, SCAN_SMEM>>>(noise, aw_prev, out);
    cv_partial_kernel<<<dim3(64, 16), 512>>>(value, out + 8192 + (size_t)NROWS);
    cv_reduce_kernel<<<16, 512>>>(out);
}

// round 17
// speedup vs baseline: 1.0251x; 1.0251x over previous
#include <cuda_runtime.h>
#include <cuda_bf16.h>
#include <cstdint>

#define Bq 16
#define Tt 8192
#define Dd 512
#define Aa 512
#define NROWS (Bq * Tt)
#define NEGINF (-3.4028234663852886e+38f)
#define EPSV 1e-8f

// -------------------- device scratch (no allocation allowed) ----------------
__device__ __align__(1024) __nv_bfloat16 g_wt[2 * Aa * Dd]; // W^T bf16: [set][a][k]
__device__ float g_qk[2][Bq][Aa];
__device__ float g_vw[2][Aa];
__device__ float g_e[2][NROWS];
__device__ float g_cvp[64][Bq][Dd];

// -------------------- helpers ----------------------------------------------
__device__ __forceinline__ uint32_t smem_to_u32(const void* p) {
    uint32_t a;
    asm("{ .reg .u64 t; cvta.to.shared.u64 t, %1; cvt.u32.u64 %0, t; }" : "=r"(a) : "l"(p));
    return a;
}
__device__ __forceinline__ float tanh_fast(float x) {
    float y;
    asm("tanh.approx.f32 %0, %1;" : "=f"(y) : "f"(x));
    return y;
}
__device__ __forceinline__ void ldsm4(uint32_t& r0, uint32_t& r1, uint32_t& r2, uint32_t& r3,
                                      uint32_t addr) {
    asm volatile("ldmatrix.sync.aligned.m8n8.x4.shared.b16 {%0,%1,%2,%3}, [%4];"
                 : "=r"(r0), "=r"(r1), "=r"(r2), "=r"(r3) : "r"(addr));
}
__device__ __forceinline__ void mma16816(float* d, const uint32_t* a, uint32_t b0, uint32_t b1) {
    asm volatile(
        "mma.sync.aligned.m16n8k16.row.col.f32.bf16.bf16.f32 "
        "{%0,%1,%2,%3}, {%4,%5,%6,%7}, {%8,%9}, {%0,%1,%2,%3};"
        : "+f"(d[0]), "+f"(d[1]), "+f"(d[2]), "+f"(d[3])
        : "r"(a[0]), "r"(a[1]), "r"(a[2]), "r"(a[3]), "r"(b0), "r"(b1));
}
__device__ __forceinline__ void cp_async16(uint32_t smem_addr, const void* gptr) {
    asm volatile("cp.async.cg.shared.global [%0], [%1], 16;"
                 :: "r"(smem_addr), "l"(__cvta_generic_to_global(gptr)) : "memory");
}
__device__ __forceinline__ void cp_async_commit() {
    asm volatile("cp.async.commit_group;" ::: "memory");
}
__device__ __forceinline__ void cp_async_wait0() {
    asm volatile("cp.async.wait_group 0;" ::: "memory");
}
__device__ __forceinline__ void cp_async_wait1() {
    asm volatile("cp.async.wait_group 1;" ::: "memory");
}

// ---------- merged prepass: vw | qk | W^T pack in one kernel ----------------
// blocks 0-1: vw(set) ; 2-33: qk(b,set) ; 34-97: wpack(k0,set). 512 threads.
__global__ void __launch_bounds__(512) prep_all_kernel(
    const float* __restrict__ query,
    const float* __restrict__ m_wk, const float* __restrict__ m_bk,
    const float* __restrict__ m_wq, const float* __restrict__ m_vv,
    const float* __restrict__ m_vg,
    const float* __restrict__ c_wk, const float* __restrict__ c_bk,
    const float* __restrict__ c_wq, const float* __restrict__ c_vv,
    const float* __restrict__ c_vg) {
    int blk = blockIdx.x;
    int tid = threadIdx.x;
    if (blk < 2) {
        // ---- v_w = vg/||vv|| * vv
        int set = blk;
        const float* vv = set ? c_vv : m_vv;
        float g = set ? __ldg(c_vg) : __ldg(m_vg);
        float v = vv[tid];
        float ss = v * v;
        __shared__ float sc[32];
        int lane = tid & 31, w = tid >> 5;
        #pragma unroll
        for (int o = 16; o > 0; o >>= 1) ss += __shfl_down_sync(0xffffffffu, ss, o);
        if (lane == 0) sc[w] = ss;
        __syncthreads();
        if (w == 0) {
            float x = (lane < 16) ? sc[lane] : 0.f;
            #pragma unroll
            for (int o = 8; o > 0; o >>= 1) x += __shfl_down_sync(0xffffffffu, x, o);
            if (lane == 0) sc[0] = x;
        }
        __syncthreads();
        g_vw[set][tid] = g / sqrtf(sc[0]) * v;
    } else if (blk < 34) {
        // ---- qk[set][b][a] = sum_d query[b,d]*wq[d,a] + bk[a]
        int id = blk - 2;
        int b = id & 15, set = id >> 4;
        const float* wq = set ? c_wq : m_wq;
        const float* bk = set ? c_bk : m_bk;
        __shared__ float qs[Dd];
        qs[tid] = query[(size_t)b * Dd + tid];
        __syncthreads();
        float acc = 0.f;
        #pragma unroll 8
        for (int d = 0; d < Dd; d++) acc = fmaf(qs[d], wq[(size_t)d * Aa + tid], acc);
        g_qk[set][b][tid] = acc + bk[tid];
    } else {
        // ---- pack W^T bf16 [set][a][k], 16 k-cols per block.
        // Stage through transposed SMEM so global writes are full 32B sectors.
        int id = blk - 34;
        int k0 = (id & 31) * 16;
        int set = id >> 5;
        const float* wk = set ? c_wk : m_wk;
        __nv_bfloat16* img = g_wt + (size_t)set * Aa * Dd;
        __shared__ __nv_bfloat16 tile[512][24]; // [a][k]; 48B rows -> uint4-aligned
        #pragma unroll
        for (int i = 0; i < 16; i++) {
            int idx = tid + i * 512;
            int kk = idx >> 9;
            int a = idx & 511;
            float v = wk[(size_t)(k0 + kk) * Aa + a]; // coalesced over a
            tile[a][kk] = __float2bfloat16_rn(v);
        }
        __syncthreads();
        // one thread per a: write 16 bf16 = 32 B contiguous, 32B-aligned
        uint4* dst = reinterpret_cast<uint4*>(img + (size_t)tid * Dd + k0);
        const uint4* src = reinterpret_cast<const uint4*>(&tile[tid][0]);
        dst[0] = src[0];
        dst[1] = src[1];
    }
}

// --- energy kernel (mma.sync bf16, 8 warps, 3-stage cp.async pipeline) ------
// SMEM: A 65536 | B 3 stages x 16384 = 49152 | e_red 256
#define SM_A 0u
#define SM_B0 65536u
#define SM_ER 114688u
#define ENERGY_SMEM 114944
__global__ void __launch_bounds__(256, 2) energy_kernel(
    const float* __restrict__ key,
    const float* __restrict__ m_vb, const float* __restrict__ m_r,
    const float* __restrict__ c_vb, const float* __restrict__ c_r) {
    extern __shared__ __align__(1024) unsigned char smem[];
    const uint32_t sbase = smem_to_u32(smem);
    const int tid = threadIdx.x;
    const int lane = tid & 31, wid = tid >> 5; // 8 warps, side-by-side in N
    const int warpN = wid * 32;                // N-slice within 256-wide nc half
    const int mtile = blockIdx.x;              // 2048 tiles of 64 rows
    const int b = mtile >> 7;

    float* e_red = reinterpret_cast<float*>(smem + SM_ER);

    // ---- A tile: 64 rows of key, fp32 -> bf16, layout (k>>6)*8KB + r*128 + (k&63)*2, xor swz
    const float* krow = key + (size_t)mtile * 64 * Dd;
    for (int idx = tid; idx < 64 * 256; idx += 256) {
        int r = idx >> 8;
        int c2 = (idx & 255) << 1;
        float2 v = *reinterpret_cast<const float2*>(krow + (size_t)r * Dd + c2);
        __nv_bfloat162 bv;
        bv.x = __float2bfloat16_rn(v.x);
        bv.y = __float2bfloat16_rn(v.y);
        uint32_t off = (uint32_t)((c2 >> 6) * 8192 + r * 128 + (c2 & 63) * 2);
        off ^= (off >> 3) & 0x70;
        *reinterpret_cast<uint32_t*>(smem + SM_A + off) = *reinterpret_cast<uint32_t*>(&bv);
    }

    // A ldmatrix per-thread base addresses (4 m16 tiles = full 64 rows)
    const int arow0 = lane & 15;
    const uint32_t alp = (uint32_t)((lane >> 4) * 16);
    const uint32_t swzA = (uint32_t)((arow0 & 7) * 16);
    uint32_t aBase[4];
    #pragma unroll
    for (int mt = 0; mt < 4; mt++)
        aBase[mt] = sbase + SM_A + (uint32_t)((arow0 + mt * 16) * 128);

    // B buffer: 256 n-rows x 32 k bf16 (64B/row); chunk c at col (c ^ ((n>>1)&3))*16.
    const int nrow = (lane & 7) + ((lane >> 4) & 1) * 8;
    const uint32_t bsw = (uint32_t)((nrow >> 1) & 3);
    const uint32_t kb = (uint32_t)((lane >> 3) & 1);
    uint32_t bRow[2];
    #pragma unroll
    for (int p = 0; p < 2; p++)
        bRow[p] = (uint32_t)((warpN + nrow + p * 16) * 64);

    // cp.async per-thread slots: 4 rows x 16B per thread per k32-step (coalesced)
    const int bn = tid >> 2;  // row 0..63 (stride 64)
    const int bc = tid & 3;   // 16B chunk 0..3
    const uint32_t bcs = (uint32_t)((bc ^ ((bn >> 1) & 3)) << 4);
    uint32_t bDst[4];
    #pragma unroll
    for (int i = 0; i < 4; i++)
        bDst[i] = sbase + SM_B0 + (uint32_t)((bn + i * 64) * 64) + bcs;

    for (int set = 0; set < 2; set++) {
        if (tid < 64) e_red[tid] = 0.f;
        __syncthreads();

        const char* wbase = reinterpret_cast<const char*>(g_wt + (size_t)set * Aa * Dd);
        const float* qkp = g_qk[set][b];
        const float* vwp = g_vw[set];
        float er[8];
        #pragma unroll
        for (int i = 0; i < 8; i++) er[i] = 0.f;

        for (int nc = 0; nc < 2; nc++) {
            const int n0 = nc * 256;
            float acc[4][4][4];
            #pragma unroll
            for (int mt = 0; mt < 4; mt++)
                #pragma unroll
                for (int nt = 0; nt < 4; nt++)
                    #pragma unroll
                    for (int q = 0; q < 4; q++) acc[mt][nt][q] = 0.f;

            // all reads of previous nc/set buffers must be done before refill
            __syncthreads();

            // prologue: stage k32 steps 0 and 1 (2 groups in flight)
            {
                const char* src = wbase + (size_t)(n0 + bn) * 1024 + bc * 16;
                #pragma unroll
                for (int i = 0; i < 4; i++)
                    cp_async16(bDst[i], src + (size_t)i * 64 * 1024);
                cp_async_commit();
                #pragma unroll
                for (int i = 0; i < 4; i++)
                    cp_async16(bDst[i] + 16384u, src + (size_t)i * 64 * 1024 + 64);
                cp_async_commit();
            }

            for (int ks = 0; ks < 16; ks++) {  // k32 steps, 3-stage pipeline
                if (ks < 15) cp_async_wait1(); else cp_async_wait0();
                __syncthreads();
                if (ks < 14) {
                    const uint32_t dstx = 16384u * (uint32_t)((ks + 2) % 3);
                    const char* src = wbase + (size_t)(n0 + bn) * 1024 + (ks + 2) * 64 + bc * 16;
                    #pragma unroll
                    for (int i = 0; i < 4; i++)
                        cp_async16(bDst[i] + dstx, src + (size_t)i * 64 * 1024);
                    cp_async_commit();
                }
                const uint32_t aChunk = (uint32_t)((ks >> 1) * 8192);
                const uint32_t aHalf = (uint32_t)((ks & 1) * 64);
                const uint32_t bBufBase = sbase + SM_B0 + 16384u * (uint32_t)(ks % 3);
                #pragma unroll
                for (int g = 0; g < 2; g++) {   // k16 halves within k32
                    uint32_t af[4][4];
                    #pragma unroll
                    for (int mt = 0; mt < 4; mt++) {
                        uint32_t addr = aBase[mt] + aChunk
                                        + ((aHalf + (uint32_t)(g * 32) + alp) ^ swzA);
                        ldsm4(af[mt][0], af[mt][1], af[mt][2], af[mt][3], addr);
                    }
                    const uint32_t bcol = (((uint32_t)(g * 2) + kb) ^ bsw) << 4;
                    uint32_t bf[2][4];
                    #pragma unroll
                    for (int p = 0; p < 2; p++) {
                        uint32_t addr = bBufBase + bRow[p] + bcol;
                        ldsm4(bf[p][0], bf[p][1], bf[p][2], bf[p][3], addr);
                    }
                    #pragma unroll
                    for (int mt = 0; mt < 4; mt++)
                        #pragma unroll
                        for (int nt = 0; nt < 4; nt++)
                            mma16816(acc[mt][nt], af[mt], bf[nt >> 1][(nt & 1) * 2],
                                     bf[nt >> 1][(nt & 1) * 2 + 1]);
                }
            }

            // epilogue: e += vw * tanh(acc + qk); qk/vw from L2-resident tables
            #pragma unroll
            for (int mt = 0; mt < 4; mt++) {
                #pragma unroll
                for (int nt = 0; nt < 4; nt++) {
                    int col = n0 + warpN + nt * 8 + (lane & 3) * 2;
                    float q0 = __ldg(qkp + col), q1 = __ldg(qkp + col + 1);
                    float w0 = __ldg(vwp + col), w1 = __ldg(vwp + col + 1);
                    er[mt * 2 + 0] += w0 * tanh_fast(acc[mt][nt][0] + q0)
                                    + w1 * tanh_fast(acc[mt][nt][1] + q1);
                    er[mt * 2 + 1] += w0 * tanh_fast(acc[mt][nt][2] + q0)
                                    + w1 * tanh_fast(acc[mt][nt][3] + q1);
                }
            }
        }

        // quad reduce (same row, different cols across lane%4)
        #pragma unroll
        for (int i = 0; i < 8; i++) {
            er[i] += __shfl_xor_sync(0xffffffffu, er[i], 1);
            er[i] += __shfl_xor_sync(0xffffffffu, er[i], 2);
        }
        if ((lane & 3) == 0) {
            int r = lane >> 2;
            #pragma unroll
            for (int mt = 0; mt < 4; mt++) {
                atomicAdd(&e_red[mt * 16 + r], er[mt * 2 + 0]);
                atomicAdd(&e_red[mt * 16 + r + 8], er[mt * 2 + 1]);
            }
        }
        __syncthreads();
        if (tid < 64) {
            float bias = set ? (__ldg(c_vb) + __ldg(c_r)) : (__ldg(m_vb) + __ldg(m_r));
            g_e[set][(size_t)mtile * 64 + tid] = e_red[tid] + bias;
        }
        __syncthreads();
    }
}

// -------------------- scan kernel (512 thr x 16 elem per batch) -------------
__device__ __forceinline__ float block_exscan512(float v, float* scratch) {
    int lane = threadIdx.x & 31, w = threadIdx.x >> 5;
    float x = v;
    #pragma unroll
    for (int o = 1; o < 32; o <<= 1) {
        float n = __shfl_up_sync(0xffffffffu, x, o);
        if (lane >= o) x += n;
    }
    if (lane == 31) scratch[w] = x;
    __syncthreads();
    if (w == 0) {
        float y = (lane < 16) ? scratch[lane] : 0.f;
        #pragma unroll
        for (int o = 1; o < 32; o <<= 1) {
            float n = __shfl_up_sync(0xffffffffu, y, o);
            if (lane >= o) y += n;
        }
        if (lane < 16) scratch[lane] = y;
    }
    __syncthreads();
    float pre = w ? scratch[w - 1] : 0.f;
    float r = pre + x - v;
    __syncthreads();
    return r;
}
__device__ __forceinline__ float block_max512(float v, float* scratch) {
    int lane = threadIdx.x & 31, w = threadIdx.x >> 5;
    float x = v;
    #pragma unroll
    for (int o = 16; o > 0; o >>= 1) x = fmaxf(x, __shfl_xor_sync(0xffffffffu, x, o));
    if (lane == 0) scratch[w] = x;
    __syncthreads();
    if (w == 0) {
        float y = (lane < 16) ? scratch[lane] : NEGINF;
        #pragma unroll
        for (int o = 16; o > 0; o >>= 1) y = fmaxf(y, __shfl_xor_sync(0xffffffffu, y, o));
        if (lane == 0) scratch[0] = y;
    }
    __syncthreads();
    float r = scratch[0];
    __syncthreads();
    return r;
}

#define SCAN_SMEM ((16384 + 32) * 4)
__global__ void __launch_bounds__(512) scan_kernel(
    const float* __restrict__ noise, const float* __restrict__ aw_prev,
    float* __restrict__ out) {
    extern __shared__ float sm[];
    float* se = sm;
    float* ratio = sm + 8192;
    float* scratch = sm + 16384;
    int b = blockIdx.x;
    int tid = threadIdx.x;
    int t0 = tid * 16;
    const float* em = g_e[0] + (size_t)b * Tt;
    const float* ec = g_e[1] + (size_t)b * Tt;
    const float* nz = noise + (size_t)b * Tt;
    const float* aw = aw_prev + (size_t)b * Tt;

    // NOTE: mask is jnp.ones(...) by construction — never read.
    float p[16], l1[16], cp[16], inn[16];
    float ts = 0.f;
    #pragma unroll
    for (int j = 0; j < 16; j++) {
        int t = t0 + j;
        float x = em[t] + nz[t];
        float pj = __fdividef(1.f, 1.f + __expf(-x));
        p[j] = pj;
        float om = fminf(fmaxf(1.f - pj, EPSV), 1.f);
        l1[j] = __logf(om);
        ts += l1[j];
    }
    float base = block_exscan512(ts, scratch);
    float run = base;
    float ts2 = 0.f;
    #pragma unroll
    for (int j = 0; j < 16; j++) {
        cp[j] = __expf(run);
        run += l1[j];
        float c = fminf(fmaxf(cp[j], EPSV), 1.f);
        inn[j] = __fdividef(aw[t0 + j], c);
        ts2 += inn[j];
    }
    float base2 = block_exscan512(ts2, scratch);
    float run2 = base2;
    #pragma unroll
    for (int j = 0; j < 16; j++) {
        run2 += inn[j];
        float a = p[j] * cp[j] * run2;
        p[j] = a;
        out[8192 + (size_t)b * Tt + t0 + j] = a;
    }

    float mx = NEGINF;
    #pragma unroll
    for (int j = 0; j < 16; j++) mx = fmaxf(mx, ec[t0 + j]);
    mx = block_max512(mx, scratch);
    #pragma unroll
    for (int j = 0; j < 16; j++) {
        int t = t0 + j;
        se[t] = fmaxf(__expf(ec[t] - mx), 1e-5f);
    }
    __syncthreads();
    #pragma unroll
    for (int j = 0; j < 16; j++) {
        int t = t0 + j;
        float d = se[t];
        if (t >= 1) d += se[t - 1];
        if (t >= 2) d += se[t - 2];
        if (t >= 3) d += se[t - 3];
        ratio[t] = __fdividef(p[j], d);
    }
    __syncthreads();
    #pragma unroll
    for (int j = 0; j < 16; j++) {
        int t = t0 + j;
        float s = ratio[t];
        if (t + 1 < Tt) s += ratio[t + 1];
        if (t + 2 < Tt) s += ratio[t + 2];
        if (t + 3 < Tt) s += ratio[t + 3];
        out[8192 + (size_t)NROWS + (size_t)b * Tt + t] = se[t] * s;
    }
}

// -------------------- cv = beta^T . value (float4 stream) -------------------
__global__ void __launch_bounds__(512) cv_partial_kernel(
    const float* __restrict__ value, const float* __restrict__ beta) {
    int tc = blockIdx.x, b = blockIdx.y;
    int d4 = threadIdx.x & 127;
    int tg = threadIdx.x >> 7;
    const float4* v = reinterpret_cast<const float4*>(
        value + ((size_t)b * Tt + (size_t)tc * 128) * Dd) + d4;
    const float* bt = beta + (size_t)b * Tt + (size_t)tc * 128 + tg * 32;
    float4 acc = make_float4(0.f, 0.f, 0.f, 0.f);
    #pragma unroll 8
    for (int t = 0; t < 32; t++) {
        float w = __ldg(bt + t);
        float4 x = __ldg(v + (size_t)(tg * 32 + t) * 128);
        acc.x = fmaf(w, x.x, acc.x);
        acc.y = fmaf(w, x.y, acc.y);
        acc.z = fmaf(w, x.z, acc.z);
        acc.w = fmaf(w, x.w, acc.w);
    }
    __shared__ float4 red[512];
    red[threadIdx.x] = acc;
    __syncthreads();
    if (tg == 0) {
        float4 a0 = red[d4], a1 = red[128 + d4], a2 = red[256 + d4], a3 = red[384 + d4];
        float4 s = make_float4(a0.x + a1.x + a2.x + a3.x,
                               a0.y + a1.y + a2.y + a3.y,
                               a0.z + a1.z + a2.z + a3.z,
                               a0.w + a1.w + a2.w + a3.w);
        reinterpret_cast<float4*>(g_cvp[tc][b])[d4] = s;
    }
}
__global__ void cv_reduce_kernel(float* __restrict__ out) {
    int b = blockIdx.x, d = threadIdx.x;
    float acc = 0.f;
    #pragma unroll
    for (int tc = 0; tc < 64; tc++) acc += g_cvp[tc][b][d];
    out[(size_t)b * Dd + d] = acc;
}

// -------------------- launch ------------------------------------------------
extern "C" void kernel_launch(void* const* d_in, const int* in_sizes, int n_in,
                              void* d_out, int out_size) {
    const float* key     = (const float*)d_in[0];
    const float* value   = (const float*)d_in[1];
    const float* query   = (const float*)d_in[2];
    const float* noise   = (const float*)d_in[3];
    const float* aw_prev = (const float*)d_in[4];
    // d_in[5] = mask: constant all-true — unused.
    const float* m_wk = (const float*)d_in[6];
    const float* m_bk = (const float*)d_in[7];
    const float* m_wq = (const float*)d_in[8];
    const float* m_vv = (const float*)d_in[9];
    const float* m_vg = (const float*)d_in[10];
    const float* m_vb = (const float*)d_in[11];
    const float* m_r  = (const float*)d_in[12];
    const float* c_wk = (const float*)d_in[13];
    const float* c_bk = (const float*)d_in[14];
    const float* c_wq = (const float*)d_in[15];
    const float* c_vv = (const float*)d_in[16];
    const float* c_vg = (const float*)d_in[17];
    const float* c_vb = (const float*)d_in[18];
    const float* c_r  = (const float*)d_in[19];
    float* out = (float*)d_out;

    cudaFuncSetAttribute(energy_kernel, cudaFuncAttributeMaxDynamicSharedMemorySize, ENERGY_SMEM);
    cudaFuncSetAttribute(scan_kernel, cudaFuncAttributeMaxDynamicSharedMemorySize, SCAN_SMEM);

    prep_all_kernel<<<98, 512>>>(query, m_wk, m_bk, m_wq, m_vv, m_vg,
                                 c_wk, c_bk, c_wq, c_vv, c_vg);
    energy_kernel<<<2048, 256, ENERGY_SMEM>>>(key, m_vb, m_r, c_vb, c_r);
    scan_kernel<<<16, 512, SCAN_SMEM>>>(noise, aw_prev, out);
    cv_partial_kernel<<<dim3(64, 16), 512>>>(value, out + 8192 + (size_t)NROWS);
    cv_reduce_kernel<<<16, 512>>>(out);
}